// round 2
// baseline (speedup 1.0000x reference)
#include <cuda_runtime.h>

// ---------------------------------------------------------------------------
// EfmLSTM round 2:
//   K1: x_proj GEMM (fp32 FFMA2, unchanged)
//   K1b: f_seq = sigmoid(sig @ forget_kernel + b_f)  (precomputed, parallel)
//   K2: persistent scan, ONE row per CTA, 256 CTAs (2 co-resident CTAs/SM),
//       recurrent weights in registers, <=84 regs for occupancy 2.
// ---------------------------------------------------------------------------

#define B_   256
#define T_   1024
#define D_   256
#define U_   128
#define G_   384   // 3*U
#define SIG_ 20
#define M_   (B_ * T_)

typedef unsigned long long ull;

// scratch: x_proj [B,T,3U] (402MB) + f_seq [B,T,U] (134MB)
__device__ float g_xproj[(size_t)M_ * G_];
__device__ float g_fseq[(size_t)M_ * U_];

// ---- packed f32x2 helpers (sm_103a FFMA2) ----
__device__ __forceinline__ ull pack2f(float lo, float hi) {
    ull r;
    asm("mov.b64 %0, {%1,%2};" : "=l"(r) : "f"(lo), "f"(hi));
    return r;
}
__device__ __forceinline__ void unpack2f(ull v, float& lo, float& hi) {
    asm("mov.b64 {%0,%1}, %2;" : "=f"(lo), "=f"(hi) : "l"(v));
}
__device__ __forceinline__ ull ffma2(ull a, ull b, ull c) {
    ull d;
    asm("fma.rn.f32x2 %0, %1, %2, %3;" : "=l"(d) : "l"(a), "l"(b), "l"(c));
    return d;
}

// ---- fast activations ----
__device__ __forceinline__ float fsig(float x) {
    return __fdividef(1.0f, 1.0f + __expf(-x));
}
__device__ __forceinline__ float ftanh(float x) {
    return 1.0f - 2.0f * __fdividef(1.0f, __expf(2.0f * x) + 1.0f);
}

// ===========================================================================
// Kernel 1: x_proj = inputs[M,256] @ input_kernel[256,384]  (fp32)
// ===========================================================================
#define BM 128
#define BN 128
#define BK 16

__global__ __launch_bounds__(256, 1)
void xproj_gemm(const float* __restrict__ A, const float* __restrict__ Bw) {
    __shared__ __align__(16) float As[BK][BM];
    __shared__ __align__(16) float Bs[BK][BN];

    const int tid = threadIdx.x;
    const int bn  = blockIdx.x;
    const int bm  = blockIdx.y;
    const int K = D_, N = G_;

    const int arow = tid >> 2;
    const int acol = (tid & 3) << 2;
    const int brow = tid >> 5;
    const int bcol = (tid & 31) << 2;
    const int tx = tid & 15, ty = tid >> 4;

    const float* Ab = A + (size_t)bm * BM * K;
    const float* Bb = Bw + bn * BN;

    float4 a0r = *(const float4*)&Ab[(size_t)arow * K + acol];
    float4 a1r = *(const float4*)&Ab[(size_t)(arow + 64) * K + acol];
    float4 b0r = *(const float4*)&Bb[(size_t)brow * N + bcol];
    float4 b1r = *(const float4*)&Bb[(size_t)(brow + 8) * N + bcol];

    ull acc[8][4];
#pragma unroll
    for (int i = 0; i < 8; i++)
#pragma unroll
        for (int j = 0; j < 4; j++) acc[i][j] = 0ULL;

    for (int kt = 0; kt < K; kt += BK) {
        As[acol + 0][arow]      = a0r.x;
        As[acol + 1][arow]      = a0r.y;
        As[acol + 2][arow]      = a0r.z;
        As[acol + 3][arow]      = a0r.w;
        As[acol + 0][arow + 64] = a1r.x;
        As[acol + 1][arow + 64] = a1r.y;
        As[acol + 2][arow + 64] = a1r.z;
        As[acol + 3][arow + 64] = a1r.w;
        *(float4*)&Bs[brow][bcol]     = b0r;
        *(float4*)&Bs[brow + 8][bcol] = b1r;
        __syncthreads();

        if (kt + BK < K) {
            a0r = *(const float4*)&Ab[(size_t)arow * K + (kt + BK) + acol];
            a1r = *(const float4*)&Ab[(size_t)(arow + 64) * K + (kt + BK) + acol];
            b0r = *(const float4*)&Bb[(size_t)(kt + BK + brow) * N + bcol];
            b1r = *(const float4*)&Bb[(size_t)(kt + BK + brow + 8) * N + bcol];
        }

#pragma unroll
        for (int k = 0; k < BK; k++) {
            float4 av0 = *(const float4*)&As[k][ty * 4];
            float4 av1 = *(const float4*)&As[k][64 + ty * 4];
            ulonglong2 bv0 = *(const ulonglong2*)&Bs[k][tx * 4];
            ulonglong2 bv1 = *(const ulonglong2*)&Bs[k][64 + tx * 4];
            float am[8] = {av0.x, av0.y, av0.z, av0.w,
                           av1.x, av1.y, av1.z, av1.w};
#pragma unroll
            for (int i = 0; i < 8; i++) {
                ull ap = pack2f(am[i], am[i]);
                acc[i][0] = ffma2(ap, bv0.x, acc[i][0]);
                acc[i][1] = ffma2(ap, bv0.y, acc[i][1]);
                acc[i][2] = ffma2(ap, bv1.x, acc[i][2]);
                acc[i][3] = ffma2(ap, bv1.y, acc[i][3]);
            }
        }
        __syncthreads();
    }

#pragma unroll
    for (int i = 0; i < 8; i++) {
        int ml = (i < 4) ? (ty * 4 + i) : (64 + ty * 4 + (i - 4));
        size_t row = (size_t)(bm * BM + ml) * G_ + bn * BN;
        float4 v;
        unpack2f(acc[i][0], v.x, v.y);
        unpack2f(acc[i][1], v.z, v.w);
        *(float4*)&g_xproj[row + tx * 4] = v;
        unpack2f(acc[i][2], v.x, v.y);
        unpack2f(acc[i][3], v.z, v.w);
        *(float4*)&g_xproj[row + 64 + tx * 4] = v;
    }
}

// ===========================================================================
// Kernel 1b: f_seq[M,U] = sigmoid(sig[M,SIG] @ fk[SIG,U] + b_f)
// 256 threads = 2 bt-rows x 128 units, 8 passes -> 16 rows per CTA.
// ===========================================================================
#define FROWS 16

__global__ __launch_bounds__(256, 4)
void fgate_kernel(const float* __restrict__ sigs,   // [M,SIG]
                  const float* __restrict__ fk,     // [SIG,U]
                  const float* __restrict__ bias)   // [4U]
{
    __shared__ float sfk[SIG_][U_];
    __shared__ float ssig[FROWS][SIG_];

    const int tid = threadIdx.x;
    const int u   = tid & (U_ - 1);
    const int lr  = tid >> 7;               // 0/1
    const size_t base = (size_t)blockIdx.x * FROWS;

    for (int i = tid; i < SIG_ * U_; i += 256)
        (&sfk[0][0])[i] = fk[i];
    for (int i = tid; i < FROWS * SIG_; i += 256)
        (&ssig[0][0])[i] = sigs[base * SIG_ + i];
    __syncthreads();

    const float bf = bias[U_ + u];
#pragma unroll
    for (int p = 0; p < FROWS / 2; p++) {
        int row = p * 2 + lr;
        float acc = bf;
#pragma unroll
        for (int s = 0; s < SIG_; s++)
            acc += ssig[row][s] * sfk[s][u];
        g_fseq[(base + row) * U_ + u] = fsig(acc);
    }
}

// ===========================================================================
// Kernel 2: persistent recurrent scan. 256 CTAs x 384 threads, ONE row each.
// Thread j owns gate column j; W_r[:,j] lives in 64 packed f32x2 registers.
// Two CTAs co-resident per SM hide each other's barrier/latency stalls.
// ===========================================================================
__global__ __launch_bounds__(384, 2)
void efm_scan(const float* __restrict__ rk,     // [U,3U]
              const float* __restrict__ bias,   // [4U]
              float* __restrict__ out)          // [B,T,U]
{
    const int j = threadIdx.x;
    const int r = blockIdx.x;

    __shared__ __align__(16) float sh[U_];   // h state
    __shared__ __align__(16) float sg[G_];   // activated gates

    // W_r column j as packed k-pairs
    ull W[64];
#pragma unroll
    for (int k2 = 0; k2 < 64; k2++)
        W[k2] = pack2f(rk[(2 * k2) * G_ + j], rk[(2 * k2 + 1) * G_ + j]);

    // gate bias: [b_i | b_c | b_o]
    float gb;
    if (j < U_)          gb = bias[j];
    else if (j < 2 * U_) gb = bias[2 * U_ + (j - U_)];
    else                 gb = bias[3 * U_ + (j - 2 * U_)];

    if (j < U_) sh[j] = 0.0f;

    const float* xp = g_xproj + (size_t)r * T_ * G_ + j;   // advances by G_
    const float* fp = g_fseq  + (size_t)r * T_ * U_ + j;   // advances by U_
    float* op = out + (size_t)r * T_ * U_ + j;             // advances by U_

    float x = xp[0];
    float fcur = (j < U_) ? fp[0] : 0.0f;
    float creg = 0.0f;
    __syncthreads();

    for (int t = 0; t < T_; t++) {
        // prefetch t+1 (hidden under the GEMV below)
        float nx = 0.0f, nf = 0.0f;
        if (t + 1 < T_) {
            nx = xp[(size_t)(t + 1) * G_];
            if (j < U_) nf = fp[(size_t)(t + 1) * U_];
        }

        // GEMV: gates[j] = h . W[:,j]  (2 packed accumulator chains)
        const ulonglong2* hp = (const ulonglong2*)sh;
        ull acA = 0ULL, acB = 0ULL;
#pragma unroll
        for (int q = 0; q < 32; q++) {
            ulonglong2 h2 = hp[q];
            acA = ffma2(h2.x, W[2 * q],     acA);
            acB = ffma2(h2.y, W[2 * q + 1], acB);
        }
        float lo, hi;
        unpack2f(acA, lo, hi); float g = lo + hi;
        unpack2f(acB, lo, hi); g += lo + hi;
        g += x + gb;

        float act = (j < U_ || j >= 2 * U_) ? fsig(g) : ftanh(g);
        sg[j] = act;
        __syncthreads();

        // state update (threads 0..127)
        if (j < U_) {
            float ig = sg[j];
            float ch = sg[U_ + j];
            float og = sg[2 * U_ + j];
            creg = fcur * creg + ig * ch;
            float hn = og * ftanh(creg);
            sh[j] = hn;
            op[(size_t)t * U_] = hn;
        }
        __syncthreads();

        x = nx;
        fcur = nf;
    }
}

// ===========================================================================
extern "C" void kernel_launch(void* const* d_in, const int* in_sizes, int n_in,
                              void* d_out, int out_size) {
    const float* inputs = (const float*)d_in[0];   // [B,T,D]
    const float* sigs   = (const float*)d_in[1];   // [B,T,SIG]
    const float* ik     = (const float*)d_in[2];   // [D,3U]
    const float* rk     = (const float*)d_in[3];   // [U,3U]
    const float* fk     = (const float*)d_in[4];   // [SIG,U]
    const float* bias   = (const float*)d_in[5];   // [4U]
    float* out = (float*)d_out;                    // [B,T,U]

    dim3 gemm_grid(G_ / BN, M_ / BM);   // (3, 2048)
    xproj_gemm<<<gemm_grid, 256>>>(inputs, ik);

    fgate_kernel<<<M_ / FROWS, 256>>>(sigs, fk, bias);

    efm_scan<<<B_, 384>>>(rk, bias, out);
}

// round 4
// speedup vs baseline: 2.2694x; 2.2694x over previous
#include <cuda_runtime.h>
#include <cuda_bf16.h>
#include <cstdint>

// ---------------------------------------------------------------------------
// EfmLSTM round 4 (no tcgen05 — plain sm_103 target):
//   K0a: inputs -> A_cat bf16 [M,512] = [ah | al]
//   K0b: input_kernel -> Bt_cat bf16 [384,768] = [bh | bh | bl]  (K contiguous)
//   K1 : x_proj via mma.sync m16n8k16 bf16, K-stacked split (logical K=768)
//   K1b: f_seq = sigmoid(sig @ forget_kernel + b_f)
//   K2 : persistent scan, 2 rows/CTA, 384 threads, W_r in registers
// ---------------------------------------------------------------------------

#define B_   256
#define T_   1024
#define D_   256
#define U_   128
#define G_   384
#define SIG_ 20
#define M_   (B_ * T_)

typedef unsigned long long ull;

__device__ float g_xproj[(size_t)M_ * G_];                  // 402 MB
__device__ float g_fseq[(size_t)M_ * U_];                   // 134 MB
__device__ __nv_bfloat16 g_acat[(size_t)M_ * 512];          // 268 MB
__device__ __nv_bfloat16 g_btcat[(size_t)G_ * 768];         // 0.6 MB

// ---- packed f32x2 helpers ----
__device__ __forceinline__ ull pack2f(float lo, float hi) {
    ull r; asm("mov.b64 %0, {%1,%2};" : "=l"(r) : "f"(lo), "f"(hi)); return r;
}
__device__ __forceinline__ void unpack2f(ull v, float& lo, float& hi) {
    asm("mov.b64 {%0,%1}, %2;" : "=f"(lo), "=f"(hi) : "l"(v));
}
__device__ __forceinline__ ull ffma2(ull a, ull b, ull c) {
    ull d; asm("fma.rn.f32x2 %0, %1, %2, %3;" : "=l"(d) : "l"(a), "l"(b), "l"(c)); return d;
}

// ---- fast activations ----
__device__ __forceinline__ float fsig(float x) {
    return __fdividef(1.0f, 1.0f + __expf(-x));
}
__device__ __forceinline__ float ftanh(float x) {
    return 1.0f - 2.0f * __fdividef(1.0f, __expf(2.0f * x) + 1.0f);
}

__device__ __forceinline__ uint32_t smem_u32(const void* p) {
    uint32_t a;
    asm("{ .reg .u64 t; cvta.to.shared.u64 t, %1; cvt.u32.u64 %0, t; }" : "=r"(a) : "l"(p));
    return a;
}

__device__ __forceinline__ void ldsm4(uint32_t* r, uint32_t addr) {
    asm volatile("ldmatrix.sync.aligned.m8n8.x4.shared.b16 {%0,%1,%2,%3}, [%4];"
        : "=r"(r[0]), "=r"(r[1]), "=r"(r[2]), "=r"(r[3]) : "r"(addr));
}

__device__ __forceinline__ void mma16816(float* d, const uint32_t* a, const uint32_t* b) {
    asm volatile(
        "mma.sync.aligned.m16n8k16.row.col.f32.bf16.bf16.f32 "
        "{%0,%1,%2,%3}, {%4,%5,%6,%7}, {%8,%9}, {%0,%1,%2,%3};"
        : "+f"(d[0]), "+f"(d[1]), "+f"(d[2]), "+f"(d[3])
        : "r"(a[0]), "r"(a[1]), "r"(a[2]), "r"(a[3]), "r"(b[0]), "r"(b[1]));
}

// ===========================================================================
// K0a: split inputs -> [ah | al]
// ===========================================================================
__global__ __launch_bounds__(256)
void conv_a(const float* __restrict__ in) {
    size_t v = (size_t)blockIdx.x * 256 + threadIdx.x;   // M*64 float4 units
    size_t m = v >> 6;
    int c4 = (int)(v & 63);
    float4 a = ((const float4*)in)[v];
    __nv_bfloat16 h0 = __float2bfloat16(a.x), h1 = __float2bfloat16(a.y);
    __nv_bfloat16 h2 = __float2bfloat16(a.z), h3 = __float2bfloat16(a.w);
    __nv_bfloat16 l0 = __float2bfloat16(a.x - __bfloat162float(h0));
    __nv_bfloat16 l1 = __float2bfloat16(a.y - __bfloat162float(h1));
    __nv_bfloat16 l2 = __float2bfloat16(a.z - __bfloat162float(h2));
    __nv_bfloat16 l3 = __float2bfloat16(a.w - __bfloat162float(h3));
    __nv_bfloat162* dst = (__nv_bfloat162*)(g_acat + m * 512 + c4 * 4);
    dst[0] = __nv_bfloat162(h0, h1);
    dst[1] = __nv_bfloat162(h2, h3);
    __nv_bfloat162* dstl = (__nv_bfloat162*)(g_acat + m * 512 + 256 + c4 * 4);
    dstl[0] = __nv_bfloat162(l0, l1);
    dstl[1] = __nv_bfloat162(l2, l3);
}

// ===========================================================================
// K0b: Bt_cat[n][0:256]=bh, [256:512]=bh, [512:768]=bl from ik[k][n]
// ===========================================================================
__global__ __launch_bounds__(384)
void conv_b(const float* __restrict__ ik) {
    int k = blockIdx.x;        // 0..255
    int n = threadIdx.x;       // 0..383
    float b = ik[(size_t)k * G_ + n];
    __nv_bfloat16 bh = __float2bfloat16(b);
    __nv_bfloat16 bl = __float2bfloat16(b - __bfloat162float(bh));
    __nv_bfloat16* row = g_btcat + (size_t)n * 768;
    row[k] = bh;
    row[256 + k] = bh;
    row[512 + k] = bl;
}

// ===========================================================================
// K1: x_proj[M,384] = A_cat(logical [M,768]) @ Bt_cat^T via mma.sync bf16.
// CTA: 64M x 128N, 12 K-chunks of 64, double-buffered SMEM (48 KB total).
// Warp w: m-strip 16*(w%4), n-strip 64*(w/4). Per warp: 1 A-frag x 8 n-tiles.
// ===========================================================================
#define SWZ(x) ((x) ^ (((x) >> 3) & 0x70))

__global__ __launch_bounds__(256, 2)
void xproj_mma(void) {
    __shared__ __align__(1024) char smA[2][8192];    // 64 rows x 128B
    __shared__ __align__(1024) char smB[2][16384];   // 128 rows x 128B

    const int tid = threadIdx.x;
    const int wid = tid >> 5;
    const int lane = tid & 31;
    const int wm = wid & 3;          // m strip: 16*wm
    const int wn = wid >> 2;         // n strip: 64*wn
    const int n0 = blockIdx.x * 128; // 0,128,256
    const size_t m0 = (size_t)blockIdx.y * 64;

    // ldmatrix per-lane geometry
    const int a_row  = wm * 16 + (lane & 15);
    const int a_hi   = lane >> 4;                 // 0/1 -> +16B chunk
    const uint32_t a_xor = (uint32_t)((a_row & 7) << 4);
    const uint32_t aAddrBase[2] = { smem_u32(&smA[0][a_row * 128]),
                                    smem_u32(&smA[1][a_row * 128]) };

    const int b_row_l = wn * 64 + (lane & 7) + ((lane >> 4) << 3);  // + p*16
    const int b_hi    = (lane >> 3) & 1;          // 0/1 -> +16B chunk
    uint32_t bAddrBase[2][4];
    uint32_t b_xor[4];
#pragma unroll
    for (int p = 0; p < 4; p++) {
        int r = b_row_l + p * 16;
        b_xor[p] = (uint32_t)((r & 7) << 4);
        bAddrBase[0][p] = smem_u32(&smB[0][r * 128]);
        bAddrBase[1][p] = smem_u32(&smB[1][r * 128]);
    }

    // LDG staging indices
    const int ar = (tid) >> 3;            // A rows: idx>>3, idx = tid + 256*i
    const int ac = tid & 7;

    float d[8][4];
#pragma unroll
    for (int p = 0; p < 8; p++)
#pragma unroll
        for (int q = 0; q < 4; q++) d[p][q] = 0.0f;

    uint4 areg[2], breg[4];

    // prologue: load chunk 0
    {
        const int akc = 0, bkc = 0;
#pragma unroll
        for (int i = 0; i < 2; i++) {
            int idx = tid + 256 * i;
            int row = idx >> 3, c16 = idx & 7;
            areg[i] = *(const uint4*)(g_acat + (m0 + row) * 512 + akc + c16 * 8);
        }
#pragma unroll
        for (int i = 0; i < 4; i++) {
            int idx = tid + 256 * i;
            int row = idx >> 3, c16 = idx & 7;
            breg[i] = *(const uint4*)(g_btcat + (size_t)(n0 + row) * 768 + bkc + c16 * 8);
        }
    }

    for (int c = 0; c < 12; c++) {
        const int buf = c & 1;

        // commit staged regs to SMEM (swizzled)
#pragma unroll
        for (int i = 0; i < 2; i++) {
            int idx = tid + 256 * i;
            int row = idx >> 3, c16 = idx & 7;
            *(uint4*)(smA[buf] + row * 128 + ((c16 * 16) ^ ((row & 7) << 4))) = areg[i];
        }
#pragma unroll
        for (int i = 0; i < 4; i++) {
            int idx = tid + 256 * i;
            int row = idx >> 3, c16 = idx & 7;
            *(uint4*)(smB[buf] + row * 128 + ((c16 * 16) ^ ((row & 7) << 4))) = breg[i];
        }
        __syncthreads();

        // prefetch next chunk
        if (c + 1 < 12) {
            const int cn = c + 1;
            const int akc = (cn < 8) ? cn * 64 : (cn - 8) * 64;
            const int bkc = cn * 64;
#pragma unroll
            for (int i = 0; i < 2; i++) {
                int idx = tid + 256 * i;
                int row = idx >> 3, c16 = idx & 7;
                areg[i] = *(const uint4*)(g_acat + (m0 + row) * 512 + akc + c16 * 8);
            }
#pragma unroll
            for (int i = 0; i < 4; i++) {
                int idx = tid + 256 * i;
                int row = idx >> 3, c16 = idx & 7;
                breg[i] = *(const uint4*)(g_btcat + (size_t)(n0 + row) * 768 + bkc + c16 * 8);
            }
        }

        // compute: 4 k-steps of 16
#pragma unroll
        for (int ks = 0; ks < 4; ks++) {
            uint32_t af[4];
            ldsm4(af, aAddrBase[buf] + (uint32_t)(((ks * 2 + a_hi) * 16) ^ a_xor));
#pragma unroll
            for (int p = 0; p < 4; p++) {
                uint32_t bf[4];
                ldsm4(bf, bAddrBase[buf][p] + (uint32_t)(((ks * 2 + b_hi) * 16) ^ b_xor[p]));
                mma16816(d[p * 2],     af, &bf[0]);
                mma16816(d[p * 2 + 1], af, &bf[2]);
            }
        }
        __syncthreads();
    }

    // epilogue: d[p][0..1] -> row, d[p][2..3] -> row+8
    const int mrow = (int)m0 + wm * 16 + (lane >> 2);
    const int colb = n0 + wn * 64 + 2 * (lane & 3);
#pragma unroll
    for (int p = 0; p < 8; p++) {
        int col = colb + p * 8;
        *(float2*)(g_xproj + (size_t)mrow * G_ + col)       = make_float2(d[p][0], d[p][1]);
        *(float2*)(g_xproj + (size_t)(mrow + 8) * G_ + col) = make_float2(d[p][2], d[p][3]);
    }
}

// ===========================================================================
// K1b: f_seq[M,U] = sigmoid(sig[M,SIG] @ fk[SIG,U] + b_f)
// ===========================================================================
#define FROWS 16
__global__ __launch_bounds__(256, 4)
void fgate_kernel(const float* __restrict__ sigs,
                  const float* __restrict__ fk,
                  const float* __restrict__ bias) {
    __shared__ float sfk[SIG_][U_];
    __shared__ float ssig[FROWS][SIG_];
    const int tid = threadIdx.x;
    const int u = tid & (U_ - 1);
    const int lr = tid >> 7;
    const size_t base = (size_t)blockIdx.x * FROWS;

    for (int i = tid; i < SIG_ * U_; i += 256) (&sfk[0][0])[i] = fk[i];
    for (int i = tid; i < FROWS * SIG_; i += 256) (&ssig[0][0])[i] = sigs[base * SIG_ + i];
    __syncthreads();

    const float bf = bias[U_ + u];
#pragma unroll
    for (int p = 0; p < FROWS / 2; p++) {
        int row = p * 2 + lr;
        float acc = bf;
#pragma unroll
        for (int s = 0; s < SIG_; s++) acc += ssig[row][s] * sfk[s][u];
        g_fseq[(base + row) * U_ + u] = fsig(acc);
    }
}

// ===========================================================================
// K2: persistent scan — 128 CTAs x 384 threads, 2 rows/CTA, W in regs.
// ===========================================================================
__global__ __launch_bounds__(384, 1)
void efm_scan(const float* __restrict__ rk,
              const float* __restrict__ bias,
              float* __restrict__ out) {
    const int j = threadIdx.x;
    const int r0 = blockIdx.x * 2;

    __shared__ __align__(16) float sh[2][U_];
    __shared__ __align__(16) float sg[2][G_];

    ull W[64];
#pragma unroll
    for (int k2 = 0; k2 < 64; k2++)
        W[k2] = pack2f(rk[(2 * k2) * G_ + j], rk[(2 * k2 + 1) * G_ + j]);

    float gb;
    if (j < U_)          gb = bias[j];
    else if (j < 2 * U_) gb = bias[2 * U_ + (j - U_)];
    else                 gb = bias[3 * U_ + (j - 2 * U_)];

    if (j < U_) { sh[0][j] = 0.0f; sh[1][j] = 0.0f; }

    const int brow = (j < U_) ? 0 : 1;
    const int u = j & (U_ - 1);
    float creg = 0.0f;

    const float* fp = g_fseq + ((size_t)(r0 + brow) * T_) * U_ + u;

    float x0 = g_xproj[((size_t)r0 * T_) * G_ + j];
    float x1 = g_xproj[((size_t)(r0 + 1) * T_) * G_ + j];
    float fcur = (j < 2 * U_) ? fp[0] : 0.0f;
    __syncthreads();

    for (int t = 0; t < T_; t++) {
        float nx0 = 0.0f, nx1 = 0.0f, nf = 0.0f;
        if (t + 1 < T_) {
            nx0 = g_xproj[((size_t)r0 * T_ + t + 1) * G_ + j];
            nx1 = g_xproj[((size_t)(r0 + 1) * T_ + t + 1) * G_ + j];
            if (j < 2 * U_) nf = fp[(size_t)(t + 1) * U_];
        }

        const ulonglong2* hp0 = (const ulonglong2*)sh[0];
        const ulonglong2* hp1 = (const ulonglong2*)sh[1];
        ull acA0 = 0ULL, acB0 = 0ULL, acA1 = 0ULL, acB1 = 0ULL;
#pragma unroll
        for (int q = 0; q < 32; q++) {
            ulonglong2 h0 = hp0[q];
            ulonglong2 h1 = hp1[q];
            acA0 = ffma2(h0.x, W[2 * q],     acA0);
            acB0 = ffma2(h0.y, W[2 * q + 1], acB0);
            acA1 = ffma2(h1.x, W[2 * q],     acA1);
            acB1 = ffma2(h1.y, W[2 * q + 1], acB1);
        }
        float lo, hi;
        unpack2f(acA0, lo, hi); float g0 = lo + hi;
        unpack2f(acB0, lo, hi); g0 += lo + hi;
        g0 += x0 + gb;
        unpack2f(acA1, lo, hi); float g1 = lo + hi;
        unpack2f(acB1, lo, hi); g1 += lo + hi;
        g1 += x1 + gb;

        float act0, act1;
        if (j < U_ || j >= 2 * U_) { act0 = fsig(g0);  act1 = fsig(g1);  }
        else                       { act0 = ftanh(g0); act1 = ftanh(g1); }
        sg[0][j] = act0;
        sg[1][j] = act1;
        __syncthreads();

        if (j < 2 * U_) {
            float ig = sg[brow][u];
            float ch = sg[brow][U_ + u];
            float og = sg[brow][2 * U_ + u];
            creg = fcur * creg + ig * ch;
            float hn = og * ftanh(creg);
            sh[brow][u] = hn;
            out[((size_t)(r0 + brow) * T_ + t) * U_ + u] = hn;
        }
        __syncthreads();

        x0 = nx0;
        x1 = nx1;
        fcur = nf;
    }
}

// ===========================================================================
extern "C" void kernel_launch(void* const* d_in, const int* in_sizes, int n_in,
                              void* d_out, int out_size) {
    const float* inputs = (const float*)d_in[0];   // [B,T,D]
    const float* sigs   = (const float*)d_in[1];   // [B,T,SIG]
    const float* ik     = (const float*)d_in[2];   // [D,3U]
    const float* rk     = (const float*)d_in[3];   // [U,3U]
    const float* fk     = (const float*)d_in[4];   // [SIG,U]
    const float* bias   = (const float*)d_in[5];   // [4U]
    float* out = (float*)d_out;

    conv_a<<<(M_ * 64) / 256, 256>>>(inputs);
    conv_b<<<D_, 384>>>(ik);
    fgate_kernel<<<M_ / FROWS, 256>>>(sigs, fk, bias);

    dim3 gg(G_ / 128, M_ / 64);   // (3, 4096)
    xproj_mma<<<gg, 256>>>();

    efm_scan<<<B_ / 2, 384>>>(rk, bias, out);
}

// round 5
// speedup vs baseline: 2.4685x; 1.0877x over previous
#include <cuda_runtime.h>
#include <cuda_bf16.h>
#include <cstdint>

// ---------------------------------------------------------------------------
// EfmLSTM round 5:
//   K0a: inputs -> A_cat bf16 [M,512] = [ah | al]
//   K0b: input_kernel -> Bt_cat bf16 [384,768] = [bh | bh | bl]
//   K1 : x_proj via mma.sync m16n8k16 bf16; CTA 128x128, warp 32x64, cp.async
//   K1b: f_seq = sigmoid(sig @ forget_kernel + b_f)
//   K2 : persistent scan (unchanged from round 4)
// ---------------------------------------------------------------------------

#define B_   256
#define T_   1024
#define D_   256
#define U_   128
#define G_   384
#define SIG_ 20
#define M_   (B_ * T_)

typedef unsigned long long ull;

__device__ float g_xproj[(size_t)M_ * G_];                  // 402 MB
__device__ float g_fseq[(size_t)M_ * U_];                   // 134 MB
__device__ __nv_bfloat16 g_acat[(size_t)M_ * 512];          // 268 MB
__device__ __nv_bfloat16 g_btcat[(size_t)G_ * 768];         // 0.6 MB

// ---- packed f32x2 helpers ----
__device__ __forceinline__ ull pack2f(float lo, float hi) {
    ull r; asm("mov.b64 %0, {%1,%2};" : "=l"(r) : "f"(lo), "f"(hi)); return r;
}
__device__ __forceinline__ void unpack2f(ull v, float& lo, float& hi) {
    asm("mov.b64 {%0,%1}, %2;" : "=f"(lo), "=f"(hi) : "l"(v));
}
__device__ __forceinline__ ull ffma2(ull a, ull b, ull c) {
    ull d; asm("fma.rn.f32x2 %0, %1, %2, %3;" : "=l"(d) : "l"(a), "l"(b), "l"(c)); return d;
}

// ---- fast activations ----
__device__ __forceinline__ float fsig(float x) {
    return __fdividef(1.0f, 1.0f + __expf(-x));
}
__device__ __forceinline__ float ftanh(float x) {
    return 1.0f - 2.0f * __fdividef(1.0f, __expf(2.0f * x) + 1.0f);
}

__device__ __forceinline__ uint32_t smem_u32(const void* p) {
    uint32_t a;
    asm("{ .reg .u64 t; cvta.to.shared.u64 t, %1; cvt.u32.u64 %0, t; }" : "=r"(a) : "l"(p));
    return a;
}

__device__ __forceinline__ void ldsm4(uint32_t* r, uint32_t addr) {
    asm volatile("ldmatrix.sync.aligned.m8n8.x4.shared.b16 {%0,%1,%2,%3}, [%4];"
        : "=r"(r[0]), "=r"(r[1]), "=r"(r[2]), "=r"(r[3]) : "r"(addr));
}

__device__ __forceinline__ void mma16816(float* d, const uint32_t* a, const uint32_t* b) {
    asm volatile(
        "mma.sync.aligned.m16n8k16.row.col.f32.bf16.bf16.f32 "
        "{%0,%1,%2,%3}, {%4,%5,%6,%7}, {%8,%9}, {%0,%1,%2,%3};"
        : "+f"(d[0]), "+f"(d[1]), "+f"(d[2]), "+f"(d[3])
        : "r"(a[0]), "r"(a[1]), "r"(a[2]), "r"(a[3]), "r"(b[0]), "r"(b[1]));
}

__device__ __forceinline__ void cpasync16(uint32_t dst, const void* src) {
    asm volatile("cp.async.cg.shared.global [%0], [%1], 16;" :: "r"(dst), "l"(src) : "memory");
}
#define CP_COMMIT() asm volatile("cp.async.commit_group;" ::: "memory")
#define CP_WAIT1()  asm volatile("cp.async.wait_group 1;" ::: "memory")
#define CP_WAIT0()  asm volatile("cp.async.wait_group 0;" ::: "memory")

// ===========================================================================
// K0a: split inputs -> [ah | al]
// ===========================================================================
__global__ __launch_bounds__(256)
void conv_a(const float* __restrict__ in) {
    size_t v = (size_t)blockIdx.x * 256 + threadIdx.x;
    size_t m = v >> 6;
    int c4 = (int)(v & 63);
    float4 a = ((const float4*)in)[v];
    __nv_bfloat16 h0 = __float2bfloat16(a.x), h1 = __float2bfloat16(a.y);
    __nv_bfloat16 h2 = __float2bfloat16(a.z), h3 = __float2bfloat16(a.w);
    __nv_bfloat16 l0 = __float2bfloat16(a.x - __bfloat162float(h0));
    __nv_bfloat16 l1 = __float2bfloat16(a.y - __bfloat162float(h1));
    __nv_bfloat16 l2 = __float2bfloat16(a.z - __bfloat162float(h2));
    __nv_bfloat16 l3 = __float2bfloat16(a.w - __bfloat162float(h3));
    __nv_bfloat162* dst = (__nv_bfloat162*)(g_acat + m * 512 + c4 * 4);
    dst[0] = __nv_bfloat162(h0, h1);
    dst[1] = __nv_bfloat162(h2, h3);
    __nv_bfloat162* dstl = (__nv_bfloat162*)(g_acat + m * 512 + 256 + c4 * 4);
    dstl[0] = __nv_bfloat162(l0, l1);
    dstl[1] = __nv_bfloat162(l2, l3);
}

// ===========================================================================
// K0b: Bt_cat[n][0:256]=bh, [256:512]=bh, [512:768]=bl from ik[k][n]
// ===========================================================================
__global__ __launch_bounds__(384)
void conv_b(const float* __restrict__ ik) {
    int k = blockIdx.x;
    int n = threadIdx.x;
    float b = ik[(size_t)k * G_ + n];
    __nv_bfloat16 bh = __float2bfloat16(b);
    __nv_bfloat16 bl = __float2bfloat16(b - __bfloat162float(bh));
    __nv_bfloat16* row = g_btcat + (size_t)n * 768;
    row[k] = bh;
    row[256 + k] = bh;
    row[512 + k] = bl;
}

// ===========================================================================
// K1: x_proj[M,384] via mma.sync bf16.
// CTA 128M x 128N, warp tile 32m x 64n (4 m-warps x 2 n-warps).
// 12 K-chunks of 64, cp.async double-buffered dynamic SMEM (64 KB).
// ===========================================================================
__global__ __launch_bounds__(256, 2)
void xproj_mma(void) {
    extern __shared__ __align__(1024) char dsm[];
    char* const smA0 = dsm;
    char* const smA1 = dsm + 16384;
    char* const smB0 = dsm + 32768;
    char* const smB1 = dsm + 49152;
    char* const smA[2] = { smA0, smA1 };
    char* const smB[2] = { smB0, smB1 };

    const int tid = threadIdx.x;
    const int wid = tid >> 5;
    const int lane = tid & 31;
    const int wm = wid & 3;            // m strip: 32*wm
    const int wn = wid >> 2;           // n strip: 64*wn
    const int n0 = blockIdx.x * 128;
    const size_t m0 = (size_t)blockIdx.y * 128;

    // ---- cp.async geometry: idx = tid + 256*i, i in 0..3 ----
    const int lrow = tid >> 3;          // + 32*i
    const int c16  = tid & 7;
    const uint32_t dxor = (uint32_t)(((lrow & 7) << 4));
    uint32_t aDst[2][4], bDst[2][4];
#pragma unroll
    for (int i = 0; i < 4; i++) {
        int row = lrow + 32 * i;
        uint32_t off = (uint32_t)(row * 128 + ((c16 * 16) ^ dxor));
        aDst[0][i] = smem_u32(smA0 + off);
        aDst[1][i] = smem_u32(smA1 + off);
        bDst[0][i] = smem_u32(smB0 + off);
        bDst[1][i] = smem_u32(smB1 + off);
    }
    const __nv_bfloat16* aSrc[4];
    const __nv_bfloat16* bSrc[4];
#pragma unroll
    for (int i = 0; i < 4; i++) {
        int row = lrow + 32 * i;
        aSrc[i] = g_acat + (m0 + row) * 512 + c16 * 8;
        bSrc[i] = g_btcat + (size_t)(n0 + row) * 768 + c16 * 8;
    }

    // ---- ldmatrix geometry ----
    const int a_row0 = wm * 32 + (lane & 15);
    const int a_hi   = lane >> 4;
    const uint32_t a_xor = (uint32_t)((a_row0 & 7) << 4);
    uint32_t aBase[2][2];
    aBase[0][0] = smem_u32(smA0 + a_row0 * 128);
    aBase[0][1] = smem_u32(smA0 + (a_row0 + 16) * 128);
    aBase[1][0] = smem_u32(smA1 + a_row0 * 128);
    aBase[1][1] = smem_u32(smA1 + (a_row0 + 16) * 128);

    const int b_row_l = wn * 64 + (lane & 7) + ((lane >> 4) << 3);
    const int b_hi    = (lane >> 3) & 1;
    const uint32_t b_xor = (uint32_t)((b_row_l & 7) << 4);
    uint32_t bBase[2][4];
#pragma unroll
    for (int p = 0; p < 4; p++) {
        bBase[0][p] = smem_u32(smB0 + (b_row_l + p * 16) * 128);
        bBase[1][p] = smem_u32(smB1 + (b_row_l + p * 16) * 128);
    }

    float d[2][8][4];
#pragma unroll
    for (int af = 0; af < 2; af++)
#pragma unroll
        for (int p = 0; p < 8; p++)
#pragma unroll
            for (int q = 0; q < 4; q++) d[af][p][q] = 0.0f;

    // ---- prologue: chunk 0 -> buf 0 ----
#pragma unroll
    for (int i = 0; i < 4; i++) cpasync16(aDst[0][i], aSrc[i]);       // akc=0
#pragma unroll
    for (int i = 0; i < 4; i++) cpasync16(bDst[0][i], bSrc[i]);       // bkc=0
    CP_COMMIT();

    for (int c = 0; c < 12; c++) {
        const int buf = c & 1;

        if (c < 11) {
            const int cn = c + 1;
            const int akc = (cn < 8) ? cn * 64 : (cn - 8) * 64;
            const int bkc = cn * 64;
#pragma unroll
            for (int i = 0; i < 4; i++) cpasync16(aDst[buf ^ 1][i], aSrc[i] + akc);
#pragma unroll
            for (int i = 0; i < 4; i++) cpasync16(bDst[buf ^ 1][i], bSrc[i] + bkc);
            CP_COMMIT();
            CP_WAIT1();
        } else {
            CP_WAIT0();
        }
        __syncthreads();

        // ---- compute 4 k-steps of 16 ----
#pragma unroll
        for (int ks = 0; ks < 4; ks++) {
            uint32_t af0[4], af1[4];
            uint32_t koffA = (uint32_t)(((ks * 2 + a_hi) * 16) ^ a_xor);
            ldsm4(af0, aBase[buf][0] + koffA);
            ldsm4(af1, aBase[buf][1] + koffA);
            uint32_t koffB = (uint32_t)(((ks * 2 + b_hi) * 16) ^ b_xor);
#pragma unroll
            for (int p = 0; p < 4; p++) {
                uint32_t bf[4];
                ldsm4(bf, bBase[buf][p] + koffB);
                mma16816(d[0][p * 2],     af0, &bf[0]);
                mma16816(d[0][p * 2 + 1], af0, &bf[2]);
                mma16816(d[1][p * 2],     af1, &bf[0]);
                mma16816(d[1][p * 2 + 1], af1, &bf[2]);
            }
        }
        __syncthreads();
    }

    // ---- epilogue ----
    const int colb = n0 + wn * 64 + 2 * (lane & 3);
#pragma unroll
    for (int af = 0; af < 2; af++) {
        const int mrow = (int)m0 + wm * 32 + af * 16 + (lane >> 2);
#pragma unroll
        for (int p = 0; p < 8; p++) {
            int col = colb + p * 8;
            *(float2*)(g_xproj + (size_t)mrow * G_ + col)       = make_float2(d[af][p][0], d[af][p][1]);
            *(float2*)(g_xproj + (size_t)(mrow + 8) * G_ + col) = make_float2(d[af][p][2], d[af][p][3]);
        }
    }
}

// ===========================================================================
// K1b: f_seq[M,U] = sigmoid(sig[M,SIG] @ fk[SIG,U] + b_f)
// ===========================================================================
#define FROWS 16
__global__ __launch_bounds__(256, 4)
void fgate_kernel(const float* __restrict__ sigs,
                  const float* __restrict__ fk,
                  const float* __restrict__ bias) {
    __shared__ float sfk[SIG_][U_];
    __shared__ float ssig[FROWS][SIG_];
    const int tid = threadIdx.x;
    const int u = tid & (U_ - 1);
    const int lr = tid >> 7;
    const size_t base = (size_t)blockIdx.x * FROWS;

    for (int i = tid; i < SIG_ * U_; i += 256) (&sfk[0][0])[i] = fk[i];
    for (int i = tid; i < FROWS * SIG_; i += 256) (&ssig[0][0])[i] = sigs[base * SIG_ + i];
    __syncthreads();

    const float bf = bias[U_ + u];
#pragma unroll
    for (int p = 0; p < FROWS / 2; p++) {
        int row = p * 2 + lr;
        float acc = bf;
#pragma unroll
        for (int s = 0; s < SIG_; s++) acc += ssig[row][s] * sfk[s][u];
        g_fseq[(base + row) * U_ + u] = fsig(acc);
    }
}

// ===========================================================================
// K2: persistent scan — 128 CTAs x 384 threads, 2 rows/CTA, W in regs.
// ===========================================================================
__global__ __launch_bounds__(384, 1)
void efm_scan(const float* __restrict__ rk,
              const float* __restrict__ bias,
              float* __restrict__ out) {
    const int j = threadIdx.x;
    const int r0 = blockIdx.x * 2;

    __shared__ __align__(16) float sh[2][U_];
    __shared__ __align__(16) float sg[2][G_];

    ull W[64];
#pragma unroll
    for (int k2 = 0; k2 < 64; k2++)
        W[k2] = pack2f(rk[(2 * k2) * G_ + j], rk[(2 * k2 + 1) * G_ + j]);

    float gb;
    if (j < U_)          gb = bias[j];
    else if (j < 2 * U_) gb = bias[2 * U_ + (j - U_)];
    else                 gb = bias[3 * U_ + (j - 2 * U_)];

    if (j < U_) { sh[0][j] = 0.0f; sh[1][j] = 0.0f; }

    const int brow = (j < U_) ? 0 : 1;
    const int u = j & (U_ - 1);
    float creg = 0.0f;

    const float* fp = g_fseq + ((size_t)(r0 + brow) * T_) * U_ + u;

    float x0 = g_xproj[((size_t)r0 * T_) * G_ + j];
    float x1 = g_xproj[((size_t)(r0 + 1) * T_) * G_ + j];
    float fcur = (j < 2 * U_) ? fp[0] : 0.0f;
    __syncthreads();

    for (int t = 0; t < T_; t++) {
        float nx0 = 0.0f, nx1 = 0.0f, nf = 0.0f;
        if (t + 1 < T_) {
            nx0 = g_xproj[((size_t)r0 * T_ + t + 1) * G_ + j];
            nx1 = g_xproj[((size_t)(r0 + 1) * T_ + t + 1) * G_ + j];
            if (j < 2 * U_) nf = fp[(size_t)(t + 1) * U_];
        }

        const ulonglong2* hp0 = (const ulonglong2*)sh[0];
        const ulonglong2* hp1 = (const ulonglong2*)sh[1];
        ull acA0 = 0ULL, acB0 = 0ULL, acA1 = 0ULL, acB1 = 0ULL;
#pragma unroll
        for (int q = 0; q < 32; q++) {
            ulonglong2 h0 = hp0[q];
            ulonglong2 h1 = hp1[q];
            acA0 = ffma2(h0.x, W[2 * q],     acA0);
            acB0 = ffma2(h0.y, W[2 * q + 1], acB0);
            acA1 = ffma2(h1.x, W[2 * q],     acA1);
            acB1 = ffma2(h1.y, W[2 * q + 1], acB1);
        }
        float lo, hi;
        unpack2f(acA0, lo, hi); float g0 = lo + hi;
        unpack2f(acB0, lo, hi); g0 += lo + hi;
        g0 += x0 + gb;
        unpack2f(acA1, lo, hi); float g1 = lo + hi;
        unpack2f(acB1, lo, hi); g1 += lo + hi;
        g1 += x1 + gb;

        float act0, act1;
        if (j < U_ || j >= 2 * U_) { act0 = fsig(g0);  act1 = fsig(g1);  }
        else                       { act0 = ftanh(g0); act1 = ftanh(g1); }
        sg[0][j] = act0;
        sg[1][j] = act1;
        __syncthreads();

        if (j < 2 * U_) {
            float ig = sg[brow][u];
            float ch = sg[brow][U_ + u];
            float og = sg[brow][2 * U_ + u];
            creg = fcur * creg + ig * ch;
            float hn = og * ftanh(creg);
            sh[brow][u] = hn;
            out[((size_t)(r0 + brow) * T_ + t) * U_ + u] = hn;
        }
        __syncthreads();

        x0 = nx0;
        x1 = nx1;
        fcur = nf;
    }
}

// ===========================================================================
extern "C" void kernel_launch(void* const* d_in, const int* in_sizes, int n_in,
                              void* d_out, int out_size) {
    const float* inputs = (const float*)d_in[0];   // [B,T,D]
    const float* sigs   = (const float*)d_in[1];   // [B,T,SIG]
    const float* ik     = (const float*)d_in[2];   // [D,3U]
    const float* rk     = (const float*)d_in[3];   // [U,3U]
    const float* fk     = (const float*)d_in[4];   // [SIG,U]
    const float* bias   = (const float*)d_in[5];   // [4U]
    float* out = (float*)d_out;

    cudaFuncSetAttribute(xproj_mma, cudaFuncAttributeMaxDynamicSharedMemorySize, 65536);

    conv_a<<<(M_ * 64) / 256, 256>>>(inputs);
    conv_b<<<D_, 384>>>(ik);
    fgate_kernel<<<M_ / FROWS, 256>>>(sigs, fk, bias);

    dim3 gg(G_ / 128, M_ / 128);   // (3, 2048)
    xproj_mma<<<gg, 256, 65536>>>();

    efm_scan<<<B_ / 2, 384>>>(rk, bias, out);
}